// round 1
// baseline (speedup 1.0000x reference)
#include <cuda_runtime.h>

// Problem constants
#define B_  4
#define K_  4
#define D_  96
#define L_  2048
#define N_  16
#define R_  6
#define C_  38          // R + 2N
#define BK_ (B_*K_)     // 16

// Scratch (device globals: allocation-free, graph-safe)
// g_dx[(bk*D + d)*L + l] = {delta, x}
// g_bc[(bk*L + l)*N + n] = {B_n, C_n}
__device__ __align__(128) float2 g_dx[BK_ * D_ * L_];   // ~25 MB
__device__ __align__(128) float2 g_bc[BK_ * L_ * N_];   // ~4 MB

// ---------------------------------------------------------------------------
// Kernel 1: input projection + dt projection + softplus.
// Grid: BK_ * (L/256) = 128 blocks of 256 threads. One thread = one (b,k,l).
// ---------------------------------------------------------------------------
__global__ __launch_bounds__(256) void k1_proj(
    const float* __restrict__ xs,     // (B,K,D,L)
    const float* __restrict__ Wx,     // (K,C,D)
    const float* __restrict__ Wdt,    // (K,D,R)
    const float* __restrict__ bias)   // (K,D)
{
    __shared__ float sWp[D_][40];   // transposed x_proj: sWp[d][c], padded to 40
    __shared__ float sWd[D_][8];    // dt_projs_weight: sWd[d][r], padded to 8
    __shared__ float sB[D_];

    const int tid = threadIdx.x;
    const int bk  = blockIdx.x >> 3;             // 16 (b,k) groups
    const int k   = bk & (K_ - 1);
    const int l   = ((blockIdx.x & 7) << 8) | tid;

    // Stage weights into shared memory
    for (int i = tid; i < C_ * D_; i += 256) {
        int c = i / D_, d = i - c * D_;
        sWp[d][c] = Wx[k * C_ * D_ + i];
    }
    for (int i = tid; i < D_ * R_; i += 256) {
        int d = i / R_, r = i - d * R_;
        sWd[d][r] = Wdt[k * D_ * R_ + i];
    }
    if (tid < D_) {
        sWp[tid][38] = 0.f; sWp[tid][39] = 0.f;
        sWd[tid][6]  = 0.f; sWd[tid][7]  = 0.f;
        sB[tid] = bias[k * D_ + tid];
    }
    __syncthreads();

    // acc[c] = sum_d xs[b,k,d,l] * Wx[k,c,d]
    float acc[40];
    #pragma unroll
    for (int c = 0; c < 40; c++) acc[c] = 0.f;

    const float* __restrict__ xp = xs + (size_t)(bk * D_) * L_ + l;
    #pragma unroll 4
    for (int d = 0; d < D_; d++) {
        float x = xp[(size_t)d * L_];                          // coalesced
        const float4* wr = reinterpret_cast<const float4*>(&sWp[d][0]);
        #pragma unroll
        for (int j = 0; j < 10; j++) {
            float4 w = wr[j];
            acc[4*j+0] = fmaf(w.x, x, acc[4*j+0]);
            acc[4*j+1] = fmaf(w.y, x, acc[4*j+1]);
            acc[4*j+2] = fmaf(w.z, x, acc[4*j+2]);
            acc[4*j+3] = fmaf(w.w, x, acc[4*j+3]);
        }
    }

    // Emit {B_n, C_n} interleaved per l (k2 reads this as one 128B warp load)
    {
        float2* __restrict__ bco = g_bc + ((size_t)bk * L_ + l) * N_;
        #pragma unroll
        for (int n = 0; n < N_; n++)
            bco[n] = make_float2(acc[R_ + n], acc[R_ + N_ + n]);
    }

    // delta[d] = softplus( sum_r Wdt[k,d,r]*dts[r] + bias[k,d] ); emit {delta, x}
    {
        float2* __restrict__ dxo = g_dx + (size_t)(bk * D_) * L_ + l;
        #pragma unroll 2
        for (int d = 0; d < D_; d++) {
            float t = sB[d];
            #pragma unroll
            for (int r = 0; r < R_; r++) t = fmaf(sWd[d][r], acc[r], t);
            float sp = (t > 20.f) ? t : log1pf(__expf(t));     // stable softplus
            float x  = xp[(size_t)d * L_];                     // L1/L2 hit (reload)
            dxo[(size_t)d * L_] = make_float2(sp, x);          // coalesced
        }
    }
}

// ---------------------------------------------------------------------------
// Kernel 2: fused selective scan. One warp per (b,k,d); lane (lane&15) owns
// state n. Halves of the warp are duplicates so shuffles stay leg-local.
// Grid: 384 blocks x 128 threads; the 4 warps of a block share (b,k) so the
// g_bc stream L1-hits across d.
// ---------------------------------------------------------------------------
__global__ __launch_bounds__(128) void k2_scan(
    const float* __restrict__ Alogs,  // (K*D, N)
    const float* __restrict__ Ds,     // (K*D)
    float* __restrict__ out)          // (B,K,D,L)
{
    const int warp = threadIdx.x >> 5;
    const int lane = threadIdx.x & 31;
    const int n    = lane & 15;
    const int bk   = blockIdx.x / 24;
    const int d    = (blockIdx.x % 24) * 4 + warp;
    const int k    = bk & (K_ - 1);
    const int kd   = k * D_ + d;

    const float A   = -__expf(Alogs[kd * N_ + n]);
    const float A2  = A * 1.4426950408889634f;      // ln->log2 for ex2.approx
    const float Dd  = Ds[kd];

    const float2* __restrict__ dxp = g_dx + (size_t)(bk * D_ + d) * L_;
    const float2* __restrict__ bcp = g_bc + (size_t)bk * L_ * N_ + n;
    float*        __restrict__ yp  = out  + (size_t)(bk * D_ + d) * L_;

    float h = 0.f;
    float yreg = 0.f;

    #pragma unroll 4
    for (int l = 0; l < L_; l++) {
        float2 bc = bcp[(size_t)l * N_];   // one 128B wavefront per warp-step
        float2 dx = dxp[l];                // uniform broadcast, L1-resident

        float dA;
        asm("ex2.approx.ftz.f32 %0, %1;" : "=f"(dA) : "f"(dx.x * A2));
        float dxu = dx.x * dx.y;           // delta * x (uniform)
        h = fmaf(dA, h, dxu * bc.x);       // h = dA*h + delta*B_n*x

        float p = h * bc.y;                // h_n * C_n
        p += __shfl_xor_sync(0xffffffffu, p, 8);
        p += __shfl_xor_sync(0xffffffffu, p, 4);
        p += __shfl_xor_sync(0xffffffffu, p, 2);
        p += __shfl_xor_sync(0xffffffffu, p, 1);

        float ysum = fmaf(Dd, dx.y, p);    // + D_d * x
        if (lane == (l & 31)) yreg = ysum; // distribute y across lanes
        if ((l & 31) == 31)                // coalesced 128B flush every 32 steps
            yp[(l & ~31) + lane] = yreg;
    }
}

// ---------------------------------------------------------------------------
extern "C" void kernel_launch(void* const* d_in, const int* in_sizes, int n_in,
                              void* d_out, int out_size)
{
    const float* xs    = (const float*)d_in[0];   // (B,K,D,L)
    const float* Alogs = (const float*)d_in[1];   // (K*D, N)
    const float* Ds    = (const float*)d_in[2];   // (K*D)
    const float* Wdt   = (const float*)d_in[3];   // (K,D,R)
    const float* bias  = (const float*)d_in[4];   // (K,D)
    const float* Wx    = (const float*)d_in[5];   // (K,C,D)
    float* out = (float*)d_out;

    k1_proj<<<BK_ * (L_ / 256), 256>>>(xs, Wx, Wdt, bias);
    k2_scan<<<(BK_ * D_) / 4, 128>>>(Alogs, Ds, out);
}

// round 2
// speedup vs baseline: 2.7846x; 2.7846x over previous
#include <cuda_runtime.h>

// Problem constants
#define B_  4
#define K_  4
#define D_  96
#define L_  2048
#define N_  16
#define R_  6
#define C_  38          // R + 2N
#define BK_ (B_*K_)     // 16
#define CH  16          // chunks along L
#define LC  (L_/CH)     // 128 steps per chunk

// Scratch (device globals: allocation-free, graph-safe)
__device__ __align__(128) float2 g_dx[BK_ * D_ * L_];        // {delta, x}   ~25 MB
__device__ __align__(128) float2 g_bc[BK_ * L_ * N_];        // {B_n, C_n}   ~4 MB
__device__ __align__(128) float2 g_pq[BK_ * D_ * CH * N_];   // {P, q}       ~3 MB
__device__ __align__(128) float  g_h0[BK_ * D_ * CH * N_];   // chunk-entry h ~1.5 MB

// ---------------------------------------------------------------------------
// Kernel 1: input projection + dt projection + softplus (unchanged from R1).
// ---------------------------------------------------------------------------
__global__ __launch_bounds__(256) void k1_proj(
    const float* __restrict__ xs,     // (B,K,D,L)
    const float* __restrict__ Wx,     // (K,C,D)
    const float* __restrict__ Wdt,    // (K,D,R)
    const float* __restrict__ bias)   // (K,D)
{
    __shared__ float sWp[D_][40];
    __shared__ float sWd[D_][8];
    __shared__ float sB[D_];

    const int tid = threadIdx.x;
    const int bk  = blockIdx.x >> 3;
    const int k   = bk & (K_ - 1);
    const int l   = ((blockIdx.x & 7) << 8) | tid;

    for (int i = tid; i < C_ * D_; i += 256) {
        int c = i / D_, d = i - c * D_;
        sWp[d][c] = Wx[k * C_ * D_ + i];
    }
    for (int i = tid; i < D_ * R_; i += 256) {
        int d = i / R_, r = i - d * R_;
        sWd[d][r] = Wdt[k * D_ * R_ + i];
    }
    if (tid < D_) {
        sWp[tid][38] = 0.f; sWp[tid][39] = 0.f;
        sWd[tid][6]  = 0.f; sWd[tid][7]  = 0.f;
        sB[tid] = bias[k * D_ + tid];
    }
    __syncthreads();

    float acc[40];
    #pragma unroll
    for (int c = 0; c < 40; c++) acc[c] = 0.f;

    const float* __restrict__ xp = xs + (size_t)(bk * D_) * L_ + l;
    #pragma unroll 4
    for (int d = 0; d < D_; d++) {
        float x = xp[(size_t)d * L_];
        const float4* wr = reinterpret_cast<const float4*>(&sWp[d][0]);
        #pragma unroll
        for (int j = 0; j < 10; j++) {
            float4 w = wr[j];
            acc[4*j+0] = fmaf(w.x, x, acc[4*j+0]);
            acc[4*j+1] = fmaf(w.y, x, acc[4*j+1]);
            acc[4*j+2] = fmaf(w.z, x, acc[4*j+2]);
            acc[4*j+3] = fmaf(w.w, x, acc[4*j+3]);
        }
    }

    {
        float2* __restrict__ bco = g_bc + ((size_t)bk * L_ + l) * N_;
        #pragma unroll
        for (int n = 0; n < N_; n++)
            bco[n] = make_float2(acc[R_ + n], acc[R_ + N_ + n]);
    }
    {
        float2* __restrict__ dxo = g_dx + (size_t)(bk * D_) * L_ + l;
        #pragma unroll 2
        for (int d = 0; d < D_; d++) {
            float t = sB[d];
            #pragma unroll
            for (int r = 0; r < R_; r++) t = fmaf(sWd[d][r], acc[r], t);
            float sp = (t > 20.f) ? t : log1pf(__expf(t));
            float x  = xp[(size_t)d * L_];
            dxo[(size_t)d * L_] = make_float2(sp, x);
        }
    }
}

// ---------------------------------------------------------------------------
// Pass A: per-chunk (P = prod dA, q = chunk-local scan). Each HALF-warp owns
// one chunk (lane 0-15 -> chunk 2*cpair, lane 16-31 -> chunk 2*cpair+1);
// lane&15 owns state n. 12288 warps.
// Block mapping: 8 warps share (bk, cpair), spanning 8 d's -> bc stream L1 reuse.
// ---------------------------------------------------------------------------
__global__ __launch_bounds__(256) void k2a_chunk(
    const float* __restrict__ Alogs)  // (K*D, N)
{
    const int warp = threadIdx.x >> 5;
    const int lane = threadIdx.x & 31;
    const int half = lane >> 4;
    const int n    = lane & 15;

    const int bk    = blockIdx.x / 96;
    const int rem   = blockIdx.x % 96;
    const int cpair = rem / 12;
    const int dg    = rem % 12;
    const int d     = dg * 8 + warp;
    const int k     = bk & (K_ - 1);
    const int kd    = k * D_ + d;
    const int c     = cpair * 2 + half;
    const int l0    = c * LC;

    const float A2 = -__expf(Alogs[kd * N_ + n]) * 1.4426950408889634f;

    const float2* __restrict__ bcp = g_bc + ((size_t)bk * L_ + l0) * N_ + n;
    const float2* __restrict__ dxp = g_dx + (size_t)(bk * D_ + d) * L_ + l0;

    float h = 0.f, P = 1.f;
    #pragma unroll 4
    for (int t = 0; t < LC; t++) {
        float2 bc = bcp[(size_t)t * N_];
        float2 dx = dxp[t];
        float dA;
        asm("ex2.approx.ftz.f32 %0, %1;" : "=f"(dA) : "f"(dx.x * A2));
        h = fmaf(dA, h, dx.x * dx.y * bc.x);
        P *= dA;
    }
    g_pq[((size_t)(bk * D_ + d) * CH + c) * N_ + n] = make_float2(P, h);
}

// ---------------------------------------------------------------------------
// Pass B: sequential combine across the 16 chunks for each (bkd, n).
// 24576 independent threads; coalesced over n.
// ---------------------------------------------------------------------------
__global__ __launch_bounds__(256) void k2b_combine()
{
    const int gtid = blockIdx.x * 256 + threadIdx.x;   // [0, BK*D*N)
    const int bkd  = gtid / N_;
    const int n    = gtid % N_;

    float h = 0.f;
    #pragma unroll
    for (int c = 0; c < CH; c++) {
        const size_t idx = ((size_t)bkd * CH + c) * N_ + n;
        g_h0[idx] = h;
        float2 pq = g_pq[idx];
        h = fmaf(pq.x, h, pq.y);
    }
}

// ---------------------------------------------------------------------------
// Pass C: re-scan each chunk from its known entry state, reduce over n with
// half-warp-local xor shuffles, emit y. Same mapping as pass A.
// ---------------------------------------------------------------------------
__global__ __launch_bounds__(256) void k2c_scan(
    const float* __restrict__ Alogs,  // (K*D, N)
    const float* __restrict__ Ds,     // (K*D)
    float* __restrict__ out)          // (B,K,D,L)
{
    const int warp = threadIdx.x >> 5;
    const int lane = threadIdx.x & 31;
    const int half = lane >> 4;
    const int n    = lane & 15;

    const int bk    = blockIdx.x / 96;
    const int rem   = blockIdx.x % 96;
    const int cpair = rem / 12;
    const int dg    = rem % 12;
    const int d     = dg * 8 + warp;
    const int k     = bk & (K_ - 1);
    const int kd    = k * D_ + d;
    const int c     = cpair * 2 + half;
    const int l0    = c * LC;

    const float A2 = -__expf(Alogs[kd * N_ + n]) * 1.4426950408889634f;
    const float Dd = Ds[kd];

    const float2* __restrict__ bcp = g_bc + ((size_t)bk * L_ + l0) * N_ + n;
    const float2* __restrict__ dxp = g_dx + (size_t)(bk * D_ + d) * L_ + l0;
    float*        __restrict__ yp  = out  + (size_t)(bk * D_ + d) * L_ + l0;

    float h = g_h0[((size_t)(bk * D_ + d) * CH + c) * N_ + n];
    float yreg = 0.f;

    #pragma unroll 4
    for (int t = 0; t < LC; t++) {
        float2 bc = bcp[(size_t)t * N_];
        float2 dx = dxp[t];
        float dA;
        asm("ex2.approx.ftz.f32 %0, %1;" : "=f"(dA) : "f"(dx.x * A2));
        h = fmaf(dA, h, dx.x * dx.y * bc.x);

        float p = h * bc.y;                       // half-warp reduce over n
        p += __shfl_xor_sync(0xffffffffu, p, 8);
        p += __shfl_xor_sync(0xffffffffu, p, 4);
        p += __shfl_xor_sync(0xffffffffu, p, 2);
        p += __shfl_xor_sync(0xffffffffu, p, 1);

        float ysum = fmaf(Dd, dx.y, p);
        if (n == (t & 15)) yreg = ysum;           // distribute y across the half
        if ((t & 15) == 15)                       // 64B flush per half every 16 steps
            yp[(t & ~15) + n] = yreg;
    }
}

// ---------------------------------------------------------------------------
extern "C" void kernel_launch(void* const* d_in, const int* in_sizes, int n_in,
                              void* d_out, int out_size)
{
    const float* xs    = (const float*)d_in[0];   // (B,K,D,L)
    const float* Alogs = (const float*)d_in[1];   // (K*D, N)
    const float* Ds    = (const float*)d_in[2];   // (K*D)
    const float* Wdt   = (const float*)d_in[3];   // (K,D,R)
    const float* bias  = (const float*)d_in[4];   // (K,D)
    const float* Wx    = (const float*)d_in[5];   // (K,C,D)
    float* out = (float*)d_out;

    k1_proj<<<BK_ * (L_ / 256), 256>>>(xs, Wx, Wdt, bias);
    k2a_chunk<<<BK_ * 96, 256>>>(Alogs);                       // 1536 blocks
    k2b_combine<<<(BK_ * D_ * N_) / 256, 256>>>();             // 96 blocks
    k2c_scan<<<BK_ * 96, 256>>>(Alogs, Ds, out);               // 1536 blocks
}

// round 3
// speedup vs baseline: 3.7096x; 1.3322x over previous
#include <cuda_runtime.h>

// Problem constants
#define B_  4
#define K_  4
#define D_  96
#define L_  2048
#define N_  16
#define R_  6
#define C_  38          // R + 2N
#define BK_ (B_*K_)     // 16
#define CH  32          // chunks along L
#define LC  (L_/CH)     // 64 steps per chunk
#define DG_ (D_/8)      // 12 d-groups of 8

// Scratch (device globals: allocation-free, graph-safe)
// g_dx[((bk*DG + dg)*L + l)*8 + o] = {delta, x} for d = dg*8+o
// g_bc[(bk*L + l)*N + n]           = {B_n, C_n}
__device__ __align__(128) float2 g_dx[BK_ * D_ * L_];        // ~25 MB
__device__ __align__(128) float2 g_bc[BK_ * L_ * N_];        // ~4 MB
__device__ __align__(128) float2 g_pq[BK_ * D_ * CH * N_];   // {P, q}
__device__ __align__(128) float  g_h0[BK_ * D_ * CH * N_];   // chunk-entry h

// ---- packed f32x2 helpers (FFMA2/FMUL2 are PTX-only) ----
typedef unsigned long long u64;
struct f2 { u64 v; };
__device__ __forceinline__ f2 mk2(float x, float y) {
    f2 r; asm("mov.b64 %0, {%1, %2};" : "=l"(r.v) : "f"(x), "f"(y)); return r;
}
__device__ __forceinline__ void un2(f2 a, float& x, float& y) {
    asm("mov.b64 {%0, %1}, %2;" : "=f"(x), "=f"(y) : "l"(a.v));
}
__device__ __forceinline__ f2 mul2(f2 a, f2 b) {
    f2 r; asm("mul.rn.f32x2 %0, %1, %2;" : "=l"(r.v) : "l"(a.v), "l"(b.v)); return r;
}
__device__ __forceinline__ f2 add2(f2 a, f2 b) {
    f2 r; asm("add.rn.f32x2 %0, %1, %2;" : "=l"(r.v) : "l"(a.v), "l"(b.v)); return r;
}
__device__ __forceinline__ f2 fma2(f2 a, f2 b, f2 c) {
    f2 r; asm("fma.rn.f32x2 %0, %1, %2, %3;" : "=l"(r.v) : "l"(a.v), "l"(b.v), "l"(c.v)); return r;
}
__device__ __forceinline__ float ex2f(float x) {
    float r; asm("ex2.approx.ftz.f32 %0, %1;" : "=f"(r) : "f"(x)); return r;
}
#define LOG2E 1.4426950408889634f

// ---------------------------------------------------------------------------
// Kernel 1: input projection + dt projection + softplus.
// Phase 1: per-thread l computes acc[38], writes bc (float4) + stages dts in smem.
// Phase 2: remapped threads write the [bk][dg][l][8] dx layout coalesced.
// ---------------------------------------------------------------------------
__global__ __launch_bounds__(256) void k1_proj(
    const float* __restrict__ xs,     // (B,K,D,L)
    const float* __restrict__ Wx,     // (K,C,D)
    const float* __restrict__ Wdt,    // (K,D,R)
    const float* __restrict__ bias)   // (K,D)
{
    __shared__ float sWp[D_][40];
    __shared__ float sWd[D_][8];
    __shared__ float sB[D_];
    __shared__ float sdts[256][8];

    const int tid  = threadIdx.x;
    const int bk   = blockIdx.x >> 3;
    const int k    = bk & (K_ - 1);
    const int lblk = (blockIdx.x & 7) << 8;
    const int l    = lblk | tid;

    for (int i = tid; i < C_ * D_; i += 256) {
        int c = i / D_, d = i - c * D_;
        sWp[d][c] = Wx[k * C_ * D_ + i];
    }
    for (int i = tid; i < D_ * R_; i += 256) {
        int d = i / R_, r = i - d * R_;
        sWd[d][r] = Wdt[k * D_ * R_ + i];
    }
    if (tid < D_) {
        sWp[tid][38] = 0.f; sWp[tid][39] = 0.f;
        sWd[tid][6]  = 0.f; sWd[tid][7]  = 0.f;
        sB[tid] = bias[k * D_ + tid];
    }
    __syncthreads();

    float acc[40];
    #pragma unroll
    for (int c = 0; c < 40; c++) acc[c] = 0.f;

    const float* __restrict__ xp = xs + (size_t)(bk * D_) * L_ + l;
    #pragma unroll 4
    for (int d = 0; d < D_; d++) {
        float x = xp[(size_t)d * L_];
        const float4* wr = reinterpret_cast<const float4*>(&sWp[d][0]);
        #pragma unroll
        for (int j = 0; j < 10; j++) {
            float4 w = wr[j];
            acc[4*j+0] = fmaf(w.x, x, acc[4*j+0]);
            acc[4*j+1] = fmaf(w.y, x, acc[4*j+1]);
            acc[4*j+2] = fmaf(w.z, x, acc[4*j+2]);
            acc[4*j+3] = fmaf(w.w, x, acc[4*j+3]);
        }
    }

    // bc out: {B_n, C_n, B_{n+1}, C_{n+1}} as float4 (8 stores)
    {
        float4* __restrict__ bco = reinterpret_cast<float4*>(g_bc) + ((size_t)bk * L_ + l) * 8;
        #pragma unroll
        for (int j = 0; j < 8; j++)
            bco[j] = make_float4(acc[R_ + 2*j],     acc[R_ + N_ + 2*j],
                                 acc[R_ + 2*j + 1], acc[R_ + N_ + 2*j + 1]);
    }
    // stage dts for phase 2
    #pragma unroll
    for (int r = 0; r < R_; r++) sdts[tid][r] = acc[r];
    __syncthreads();

    // Phase 2: thread = (lq = tid>>3, o = tid&7)
    const int lq = tid >> 3;
    const int o  = tid & 7;
    for (int lc = 0; lc < 8; lc++) {
        const int lt = lc * 32 + lq;          // l within block [0,256)
        const int l2 = lblk + lt;
        #pragma unroll 2
        for (int dg = 0; dg < DG_; dg++) {
            const int d = dg * 8 + o;
            float t = sB[d];
            #pragma unroll
            for (int r = 0; r < R_; r++) t = fmaf(sWd[d][r], sdts[lt][r], t);
            float sp = (t > 15.f) ? t : __logf(1.f + __expf(t));
            float x  = xs[((size_t)bk * D_ + d) * L_ + l2];
            g_dx[(((size_t)bk * DG_ + dg) * L_ + l2) * 8 + o] = make_float2(sp, x);
        }
    }
}

// ---------------------------------------------------------------------------
// Pass A: per-chunk local scan q (h0=0) and decay P = exp2(A2 * sum(delta)).
// Warp covers 8 d (octant o) x 16 n (4 per lane, quad jj) for one (bk, chunk).
// Block = 4 warps sharing (bk, c) -> bc L1 reuse. Grid 16*32*3 = 1536.
// ---------------------------------------------------------------------------
__global__ __launch_bounds__(128) void k2a_chunk(
    const float* __restrict__ Alogs)  // (K*D, N)
{
    const int lane = threadIdx.x & 31;
    const int warp = threadIdx.x >> 5;
    const int o    = lane >> 2;
    const int jj   = lane & 3;
    const int g3   = blockIdx.x % 3;
    const int c    = (blockIdx.x / 3) & (CH - 1);
    const int bk   = blockIdx.x / (3 * CH);
    const int dg   = g3 * 4 + warp;
    const int d    = dg * 8 + o;
    const int k    = bk & (K_ - 1);
    const int kd   = k * D_ + d;
    const int n0   = jj * 4;
    const int l0   = c * LC;

    float4 al = *reinterpret_cast<const float4*>(&Alogs[kd * N_ + n0]);
    const f2 a01 = mk2(-__expf(al.x) * LOG2E, -__expf(al.y) * LOG2E);
    const f2 a23 = mk2(-__expf(al.z) * LOG2E, -__expf(al.w) * LOG2E);

    const float4* __restrict__ bcp = reinterpret_cast<const float4*>(g_bc)
                                     + ((size_t)bk * L_ + l0) * 8 + jj * 2;
    const float2* __restrict__ dxp = g_dx + (((size_t)bk * DG_ + dg) * L_ + l0) * 8 + o;

    f2 h01 = mk2(0.f, 0.f), h23 = mk2(0.f, 0.f);
    float dsum = 0.f;

    #pragma unroll 4
    for (int t = 0; t < LC; t++) {
        float4 bc0 = bcp[(size_t)t * 8];
        float4 bc1 = bcp[(size_t)t * 8 + 1];
        float2 dx  = dxp[(size_t)t * 8];

        f2 dd  = mk2(dx.x, dx.x);
        float g0, g1, g2, g3f;
        un2(mul2(dd, a01), g0, g1);
        un2(mul2(dd, a23), g2, g3f);
        f2 dA01 = mk2(ex2f(g0), ex2f(g1));
        f2 dA23 = mk2(ex2f(g2), ex2f(g3f));

        float dxu = dx.x * dx.y;
        f2 du  = mk2(dxu, dxu);
        f2 b01 = mk2(bc0.x, bc0.z);
        f2 b23 = mk2(bc1.x, bc1.z);
        h01 = fma2(dA01, h01, mul2(du, b01));
        h23 = fma2(dA23, h23, mul2(du, b23));
        dsum += dx.x;
    }

    float a0, a1, a2, a3;
    un2(a01, a0, a1); un2(a23, a2, a3);
    float q0, q1, q2, q3;
    un2(h01, q0, q1); un2(h23, q2, q3);
    float4* dst = reinterpret_cast<float4*>(g_pq)
                  + ((((size_t)bk * D_ + d) * CH + c) * N_ + n0) / 2;
    dst[0] = make_float4(ex2f(a0 * dsum), q0, ex2f(a1 * dsum), q1);
    dst[1] = make_float4(ex2f(a2 * dsum), q2, ex2f(a3 * dsum), q3);
}

// ---------------------------------------------------------------------------
// Pass B: sequential combine across CH chunks for each (bkd, n).
// ---------------------------------------------------------------------------
__global__ __launch_bounds__(256) void k2b_combine()
{
    const int gtid = blockIdx.x * 256 + threadIdx.x;   // [0, BK*D*N)
    const int bkd  = gtid / N_;
    const int n    = gtid % N_;

    float h = 0.f;
    #pragma unroll
    for (int c = 0; c < CH; c++) {
        const size_t idx = ((size_t)bkd * CH + c) * N_ + n;
        g_h0[idx] = h;
        float2 pq = g_pq[idx];
        h = fmaf(pq.x, h, pq.y);
    }
}

// ---------------------------------------------------------------------------
// Pass C: re-scan each chunk from known entry state, quad-reduce over n,
// stage y in float4 over 16-step windows, flush as STG.128.
// Same warp/lane mapping as pass A.
// ---------------------------------------------------------------------------
__global__ __launch_bounds__(128) void k2c_scan(
    const float* __restrict__ Alogs,  // (K*D, N)
    const float* __restrict__ Ds,     // (K*D)
    float* __restrict__ out)          // (B,K,D,L)
{
    const int lane = threadIdx.x & 31;
    const int warp = threadIdx.x >> 5;
    const int o    = lane >> 2;
    const int jj   = lane & 3;
    const int g3   = blockIdx.x % 3;
    const int c    = (blockIdx.x / 3) & (CH - 1);
    const int bk   = blockIdx.x / (3 * CH);
    const int dg   = g3 * 4 + warp;
    const int d    = dg * 8 + o;
    const int k    = bk & (K_ - 1);
    const int kd   = k * D_ + d;
    const int n0   = jj * 4;
    const int l0   = c * LC;

    float4 al = *reinterpret_cast<const float4*>(&Alogs[kd * N_ + n0]);
    const f2 a01 = mk2(-__expf(al.x) * LOG2E, -__expf(al.y) * LOG2E);
    const f2 a23 = mk2(-__expf(al.z) * LOG2E, -__expf(al.w) * LOG2E);
    const float Dd = Ds[kd];

    const float4* __restrict__ bcp = reinterpret_cast<const float4*>(g_bc)
                                     + ((size_t)bk * L_ + l0) * 8 + jj * 2;
    const float2* __restrict__ dxp = g_dx + (((size_t)bk * DG_ + dg) * L_ + l0) * 8 + o;
    float* __restrict__ yp = out + ((size_t)bk * D_ + d) * L_ + l0;

    float4 h0v = *reinterpret_cast<const float4*>(
        &g_h0[(((size_t)bk * D_ + d) * CH + c) * N_ + n0]);
    f2 h01 = mk2(h0v.x, h0v.y), h23 = mk2(h0v.z, h0v.w);

    for (int tw = 0; tw < LC / 16; tw++) {
        float y0 = 0.f, y1 = 0.f, y2 = 0.f, y3 = 0.f;
        #pragma unroll
        for (int tt = 0; tt < 16; tt++) {
            const int t = tw * 16 + tt;
            float4 bc0 = bcp[(size_t)t * 8];
            float4 bc1 = bcp[(size_t)t * 8 + 1];
            float2 dx  = dxp[(size_t)t * 8];

            f2 dd = mk2(dx.x, dx.x);
            float g0, g1, g2, g3f;
            un2(mul2(dd, a01), g0, g1);
            un2(mul2(dd, a23), g2, g3f);
            f2 dA01 = mk2(ex2f(g0), ex2f(g1));
            f2 dA23 = mk2(ex2f(g2), ex2f(g3f));

            float dxu = dx.x * dx.y;
            f2 du  = mk2(dxu, dxu);
            f2 b01 = mk2(bc0.x, bc0.z);
            f2 b23 = mk2(bc1.x, bc1.z);
            h01 = fma2(dA01, h01, mul2(du, b01));
            h23 = fma2(dA23, h23, mul2(du, b23));

            f2 c01 = mk2(bc0.y, bc0.w);
            f2 c23 = mk2(bc1.y, bc1.w);
            f2 ps2 = add2(mul2(h01, c01), mul2(h23, c23));
            float pa, pb; un2(ps2, pa, pb);
            float p = pa + pb;
            p += __shfl_xor_sync(0xffffffffu, p, 1);
            p += __shfl_xor_sync(0xffffffffu, p, 2);
            float ysum = fmaf(Dd, dx.y, p);

            // lane jj keeps steps [jj*4, jj*4+4) of this window
            if (jj == (tt >> 2)) {
                if      ((tt & 3) == 0) y0 = ysum;
                else if ((tt & 3) == 1) y1 = ysum;
                else if ((tt & 3) == 2) y2 = ysum;
                else                    y3 = ysum;
            }
        }
        *reinterpret_cast<float4*>(yp + tw * 16 + jj * 4) = make_float4(y0, y1, y2, y3);
    }
}

// ---------------------------------------------------------------------------
extern "C" void kernel_launch(void* const* d_in, const int* in_sizes, int n_in,
                              void* d_out, int out_size)
{
    const float* xs    = (const float*)d_in[0];   // (B,K,D,L)
    const float* Alogs = (const float*)d_in[1];   // (K*D, N)
    const float* Ds    = (const float*)d_in[2];   // (K*D)
    const float* Wdt   = (const float*)d_in[3];   // (K,D,R)
    const float* bias  = (const float*)d_in[4];   // (K,D)
    const float* Wx    = (const float*)d_in[5];   // (K,C,D)
    float* out = (float*)d_out;

    k1_proj<<<BK_ * (L_ / 256), 256>>>(xs, Wx, Wdt, bias);
    k2a_chunk<<<BK_ * CH * 3, 128>>>(Alogs);                   // 1536 blocks
    k2b_combine<<<(BK_ * D_ * N_) / 256, 256>>>();             // 96 blocks
    k2c_scan<<<BK_ * CH * 3, 128>>>(Alogs, Ds, out);           // 1536 blocks
}

// round 4
// speedup vs baseline: 4.6841x; 1.2627x over previous
#include <cuda_runtime.h>

// Problem constants
#define B_  4
#define K_  4
#define D_  96
#define L_  2048
#define N_  16
#define R_  6
#define C_  38          // R + 2N
#define BK_ (B_*K_)     // 16
#define CH  32          // chunks along L
#define LC  (L_/CH)     // 64 steps per chunk
#define DG_ (D_/8)      // 12 d-groups of 8
#define W_  16          // pipeline window (steps)
#define NW  (LC/W_)     // 4 windows per chunk

// Scratch (device globals: allocation-free, graph-safe)
// g_dx[((bk*DG + dg)*L + l)*8 + o] = {delta, x} for d = dg*8+o
// g_bc[(bk*L + l)*N + n]           = {B_n, C_n}
__device__ __align__(128) float2 g_dx[BK_ * D_ * L_];        // ~25 MB
__device__ __align__(128) float2 g_bc[BK_ * L_ * N_];        // ~4 MB
__device__ __align__(128) float2 g_pq[BK_ * D_ * CH * N_];   // {P, q}
__device__ __align__(128) float  g_h0[BK_ * D_ * CH * N_];   // chunk-entry h

// ---- packed f32x2 helpers (FFMA2/FMUL2 are PTX-only) ----
typedef unsigned long long u64;
struct f2 { u64 v; };
__device__ __forceinline__ f2 mk2(float x, float y) {
    f2 r; asm("mov.b64 %0, {%1, %2};" : "=l"(r.v) : "f"(x), "f"(y)); return r;
}
__device__ __forceinline__ void un2(f2 a, float& x, float& y) {
    asm("mov.b64 {%0, %1}, %2;" : "=f"(x), "=f"(y) : "l"(a.v));
}
__device__ __forceinline__ f2 mul2(f2 a, f2 b) {
    f2 r; asm("mul.rn.f32x2 %0, %1, %2;" : "=l"(r.v) : "l"(a.v), "l"(b.v)); return r;
}
__device__ __forceinline__ f2 add2(f2 a, f2 b) {
    f2 r; asm("add.rn.f32x2 %0, %1, %2;" : "=l"(r.v) : "l"(a.v), "l"(b.v)); return r;
}
__device__ __forceinline__ f2 fma2(f2 a, f2 b, f2 c) {
    f2 r; asm("fma.rn.f32x2 %0, %1, %2, %3;" : "=l"(r.v) : "l"(a.v), "l"(b.v), "l"(c.v)); return r;
}
__device__ __forceinline__ float ex2f(float x) {
    float r; asm("ex2.approx.ftz.f32 %0, %1;" : "=f"(r) : "f"(x)); return r;
}
#define LOG2E 1.4426950408889634f

// ---- cp.async helpers ----
__device__ __forceinline__ void cpa16(unsigned saddr, const void* gptr) {
    asm volatile("cp.async.cg.shared.global [%0], [%1], 16;" :: "r"(saddr), "l"(gptr));
}
__device__ __forceinline__ void cpa_commit() {
    asm volatile("cp.async.commit_group;");
}
__device__ __forceinline__ void cpa_wait1() {
    asm volatile("cp.async.wait_group 1;");
}

// ---------------------------------------------------------------------------
// Kernel 1: input projection + dt projection + softplus.
// 256 blocks; block = (bk, 128-l tile). Half-warps split the d-sum (48 d each)
// and combine acc via one xor-16 shuffle round.
// ---------------------------------------------------------------------------
__global__ __launch_bounds__(256) void k1_proj(
    const float* __restrict__ xs,     // (B,K,D,L)
    const float* __restrict__ Wx,     // (K,C,D)
    const float* __restrict__ Wdt,    // (K,D,R)
    const float* __restrict__ bias)   // (K,D)
{
    __shared__ float sWp[D_][40];
    __shared__ float sWd[D_][8];
    __shared__ float sB[D_];
    __shared__ float sdts[128][8];

    const int tid  = threadIdx.x;
    const int lane = tid & 31;
    const int warp = tid >> 5;
    const int bk   = blockIdx.x >> 4;
    const int k    = bk & (K_ - 1);
    const int lblk = (blockIdx.x & 15) << 7;      // 128 l per block
    const int half = lane >> 4;
    const int li   = (warp << 4) | (lane & 15);   // [0,128)
    const int l    = lblk + li;

    for (int i = tid; i < C_ * D_; i += 256) {
        int c = i / D_, d = i - c * D_;
        sWp[d][c] = Wx[k * C_ * D_ + i];
    }
    for (int i = tid; i < D_ * R_; i += 256) {
        int d = i / R_, r = i - d * R_;
        sWd[d][r] = Wdt[k * D_ * R_ + i];
    }
    if (tid < D_) {
        sWp[tid][38] = 0.f; sWp[tid][39] = 0.f;
        sWd[tid][6]  = 0.f; sWd[tid][7]  = 0.f;
        sB[tid] = bias[k * D_ + tid];
    }
    __syncthreads();

    float acc[40];
    #pragma unroll
    for (int c = 0; c < 40; c++) acc[c] = 0.f;

    // Each half-warp sums 48 d's
    const float* __restrict__ xp = xs + ((size_t)bk * D_ + half * 48) * L_ + l;
    #pragma unroll 8
    for (int dd = 0; dd < 48; dd++) {
        float x = xp[(size_t)dd * L_];
        const float4* wr = reinterpret_cast<const float4*>(&sWp[half * 48 + dd][0]);
        #pragma unroll
        for (int j = 0; j < 10; j++) {
            float4 w = wr[j];
            acc[4*j+0] = fmaf(w.x, x, acc[4*j+0]);
            acc[4*j+1] = fmaf(w.y, x, acc[4*j+1]);
            acc[4*j+2] = fmaf(w.z, x, acc[4*j+2]);
            acc[4*j+3] = fmaf(w.w, x, acc[4*j+3]);
        }
    }
    // combine the two halves
    #pragma unroll
    for (int c = 0; c < C_; c++)
        acc[c] += __shfl_xor_sync(0xffffffffu, acc[c], 16);

    // bc out: each half stores 4 of the 8 float4s
    {
        float4* __restrict__ bco = reinterpret_cast<float4*>(g_bc)
                                   + ((size_t)bk * L_ + l) * 8 + half * 4;
        #pragma unroll
        for (int j2 = 0; j2 < 4; j2++) {
            int j = half * 4 + j2;
            bco[j2] = make_float4(acc[R_ + 2*j],     acc[R_ + N_ + 2*j],
                                  acc[R_ + 2*j + 1], acc[R_ + N_ + 2*j + 1]);
        }
    }
    if (half == 0) {
        #pragma unroll
        for (int r = 0; r < R_; r++) sdts[li][r] = acc[r];
    }
    __syncthreads();

    // Phase 2: thread = (lq = tid>>3 in [0,32), o = tid&7); 4 l's each
    const int lq = tid >> 3;
    const int o  = tid & 7;
    #pragma unroll
    for (int i = 0; i < 4; i++) {
        const int lt = lq + 32 * i;
        const int l2 = lblk + lt;
        #pragma unroll 2
        for (int dg = 0; dg < DG_; dg++) {
            const int d = dg * 8 + o;
            float t = sB[d];
            #pragma unroll
            for (int r = 0; r < R_; r++) t = fmaf(sWd[d][r], sdts[lt][r], t);
            float sp = (t > 15.f) ? t : __logf(1.f + __expf(t));
            float x  = xs[((size_t)bk * D_ + d) * L_ + l2];
            g_dx[(((size_t)bk * DG_ + dg) * L_ + l2) * 8 + o] = make_float2(sp, x);
        }
    }
}

// ---------------------------------------------------------------------------
// Pass A: per-chunk local scan q (h0=0) and decay P = exp2(A2 * sum(delta)).
// cp.async 3-stage pipeline staging bc+dx windows in smem.
// Warp covers 8 d (octant o) x 16 n (quad jj); block = 4 warps (dgs) on (bk,c).
// ---------------------------------------------------------------------------
__global__ __launch_bounds__(128) void k2a_chunk(
    const float* __restrict__ Alogs)  // (K*D, N)
{
    __shared__ __align__(16) float4 s_bc[3][W_][8];
    __shared__ __align__(16) float4 s_dx4[3][256];

    const int tid  = threadIdx.x;
    const int lane = tid & 31;
    const int warp = tid >> 5;
    const int o    = lane >> 2;
    const int jj   = lane & 3;
    const int g3   = blockIdx.x % 3;
    const int c    = (blockIdx.x / 3) & (CH - 1);
    const int bk   = blockIdx.x / (3 * CH);
    const int dg   = g3 * 4 + warp;
    const int d    = dg * 8 + o;
    const int k    = bk & (K_ - 1);
    const int kd   = k * D_ + d;
    const int n0   = jj * 4;
    const int l0   = c * LC;

    float4 al = *reinterpret_cast<const float4*>(&Alogs[kd * N_ + n0]);
    const f2 a01 = mk2(-__expf(al.x) * LOG2E, -__expf(al.y) * LOG2E);
    const f2 a23 = mk2(-__expf(al.z) * LOG2E, -__expf(al.w) * LOG2E);

    const float4* __restrict__ bcsrc = reinterpret_cast<const float4*>(g_bc)
                                       + ((size_t)bk * L_ + l0) * 8;
    const unsigned sb_base = (unsigned)__cvta_generic_to_shared(&s_bc[0][0][0]);
    const unsigned sd_base = (unsigned)__cvta_generic_to_shared(&s_dx4[0][0]);

    const int pt = tid >> 3, pj = tid & 7;             // bc producer coords
    const int dgl0 = tid >> 6, r0 = tid & 63;          // dx producer coords (i=0)
    const int dgl1 = (tid + 128) >> 6, r1 = (tid + 128) & 63;

    // producer lambda (macro-style)
    #define ISSUE_WIN(tw_) do {                                                   \
        int st_ = (tw_) % 3;                                                      \
        cpa16(sb_base + (unsigned)(((st_ * W_ + pt) * 8 + pj) * 16),              \
              bcsrc + ((tw_) * W_ + pt) * 8 + pj);                                \
        cpa16(sd_base + (unsigned)((st_ * 256 + tid) * 16),                       \
              reinterpret_cast<const float4*>(g_dx)                               \
              + (((size_t)bk * DG_ + (g3 * 4 + dgl0)) * L_ + l0 + (tw_) * W_) * 4 + r0); \
        cpa16(sd_base + (unsigned)((st_ * 256 + tid + 128) * 16),                 \
              reinterpret_cast<const float4*>(g_dx)                               \
              + (((size_t)bk * DG_ + (g3 * 4 + dgl1)) * L_ + l0 + (tw_) * W_) * 4 + r1); \
    } while (0)

    ISSUE_WIN(0); cpa_commit();
    ISSUE_WIN(1); cpa_commit();

    f2 h01 = mk2(0.f, 0.f), h23 = mk2(0.f, 0.f);
    float dsum = 0.f;

    for (int tw = 0; tw < NW; tw++) {
        cpa_wait1();
        __syncthreads();
        if (tw + 2 < NW) { ISSUE_WIN(tw + 2); }
        cpa_commit();

        const int st = tw % 3;
        const float2* __restrict__ sdx = reinterpret_cast<const float2*>(&s_dx4[st][0]);
        #pragma unroll
        for (int tt = 0; tt < W_; tt++) {
            float4 bc0 = s_bc[st][tt][jj * 2];
            float4 bc1 = s_bc[st][tt][jj * 2 + 1];
            float2 dx  = sdx[(warp * W_ + tt) * 8 + o];

            f2 dd = mk2(dx.x, dx.x);
            float g0, g1, g2, g3f;
            un2(mul2(dd, a01), g0, g1);
            un2(mul2(dd, a23), g2, g3f);
            f2 dA01 = mk2(ex2f(g0), ex2f(g1));
            f2 dA23 = mk2(ex2f(g2), ex2f(g3f));

            float dxu = dx.x * dx.y;
            f2 du  = mk2(dxu, dxu);
            f2 b01 = mk2(bc0.x, bc0.z);
            f2 b23 = mk2(bc1.x, bc1.z);
            h01 = fma2(dA01, h01, mul2(du, b01));
            h23 = fma2(dA23, h23, mul2(du, b23));
            dsum += dx.x;
        }
        __syncthreads();
    }
    #undef ISSUE_WIN

    float a0, a1, a2, a3;
    un2(a01, a0, a1); un2(a23, a2, a3);
    float q0, q1, q2, q3;
    un2(h01, q0, q1); un2(h23, q2, q3);
    float4* dst = reinterpret_cast<float4*>(g_pq)
                  + ((((size_t)bk * D_ + d) * CH + c) * N_ + n0) / 2;
    dst[0] = make_float4(ex2f(a0 * dsum), q0, ex2f(a1 * dsum), q1);
    dst[1] = make_float4(ex2f(a2 * dsum), q2, ex2f(a3 * dsum), q3);
}

// ---------------------------------------------------------------------------
// Pass B: sequential combine across CH chunks for each (bkd, n).
// ---------------------------------------------------------------------------
__global__ __launch_bounds__(256) void k2b_combine()
{
    const int gtid = blockIdx.x * 256 + threadIdx.x;   // [0, BK*D*N)
    const int bkd  = gtid / N_;
    const int n    = gtid % N_;

    float h = 0.f;
    #pragma unroll
    for (int c = 0; c < CH; c++) {
        const size_t idx = ((size_t)bkd * CH + c) * N_ + n;
        g_h0[idx] = h;
        float2 pq = g_pq[idx];
        h = fmaf(pq.x, h, pq.y);
    }
}

// ---------------------------------------------------------------------------
// Pass C: re-scan from known entry state with the same cp.async pipeline;
// quad-reduce over n; y staged per lane, STG.128 per 16-step window.
// ---------------------------------------------------------------------------
__global__ __launch_bounds__(128) void k2c_scan(
    const float* __restrict__ Alogs,  // (K*D, N)
    const float* __restrict__ Ds,     // (K*D)
    float* __restrict__ out)          // (B,K,D,L)
{
    __shared__ __align__(16) float4 s_bc[3][W_][8];
    __shared__ __align__(16) float4 s_dx4[3][256];

    const int tid  = threadIdx.x;
    const int lane = tid & 31;
    const int warp = tid >> 5;
    const int o    = lane >> 2;
    const int jj   = lane & 3;
    const int g3   = blockIdx.x % 3;
    const int c    = (blockIdx.x / 3) & (CH - 1);
    const int bk   = blockIdx.x / (3 * CH);
    const int dg   = g3 * 4 + warp;
    const int d    = dg * 8 + o;
    const int k    = bk & (K_ - 1);
    const int kd   = k * D_ + d;
    const int n0   = jj * 4;
    const int l0   = c * LC;

    float4 al = *reinterpret_cast<const float4*>(&Alogs[kd * N_ + n0]);
    const f2 a01 = mk2(-__expf(al.x) * LOG2E, -__expf(al.y) * LOG2E);
    const f2 a23 = mk2(-__expf(al.z) * LOG2E, -__expf(al.w) * LOG2E);
    const float Dd = Ds[kd];

    const float4* __restrict__ bcsrc = reinterpret_cast<const float4*>(g_bc)
                                       + ((size_t)bk * L_ + l0) * 8;
    float* __restrict__ yp = out + ((size_t)bk * D_ + d) * L_ + l0;

    const unsigned sb_base = (unsigned)__cvta_generic_to_shared(&s_bc[0][0][0]);
    const unsigned sd_base = (unsigned)__cvta_generic_to_shared(&s_dx4[0][0]);

    const int pt = tid >> 3, pj = tid & 7;
    const int dgl0 = tid >> 6, r0 = tid & 63;
    const int dgl1 = (tid + 128) >> 6, r1 = (tid + 128) & 63;

    #define ISSUE_WIN(tw_) do {                                                   \
        int st_ = (tw_) % 3;                                                      \
        cpa16(sb_base + (unsigned)(((st_ * W_ + pt) * 8 + pj) * 16),              \
              bcsrc + ((tw_) * W_ + pt) * 8 + pj);                                \
        cpa16(sd_base + (unsigned)((st_ * 256 + tid) * 16),                       \
              reinterpret_cast<const float4*>(g_dx)                               \
              + (((size_t)bk * DG_ + (g3 * 4 + dgl0)) * L_ + l0 + (tw_) * W_) * 4 + r0); \
        cpa16(sd_base + (unsigned)((st_ * 256 + tid + 128) * 16),                 \
              reinterpret_cast<const float4*>(g_dx)                               \
              + (((size_t)bk * DG_ + (g3 * 4 + dgl1)) * L_ + l0 + (tw_) * W_) * 4 + r1); \
    } while (0)

    ISSUE_WIN(0); cpa_commit();
    ISSUE_WIN(1); cpa_commit();

    float4 h0v = *reinterpret_cast<const float4*>(
        &g_h0[(((size_t)bk * D_ + d) * CH + c) * N_ + n0]);
    f2 h01 = mk2(h0v.x, h0v.y), h23 = mk2(h0v.z, h0v.w);

    for (int tw = 0; tw < NW; tw++) {
        cpa_wait1();
        __syncthreads();
        if (tw + 2 < NW) { ISSUE_WIN(tw + 2); }
        cpa_commit();

        const int st = tw % 3;
        const float2* __restrict__ sdx = reinterpret_cast<const float2*>(&s_dx4[st][0]);

        float y0 = 0.f, y1 = 0.f, y2 = 0.f, y3 = 0.f;
        #pragma unroll
        for (int tt = 0; tt < W_; tt++) {
            float4 bc0 = s_bc[st][tt][jj * 2];
            float4 bc1 = s_bc[st][tt][jj * 2 + 1];
            float2 dx  = sdx[(warp * W_ + tt) * 8 + o];

            f2 dd = mk2(dx.x, dx.x);
            float g0, g1, g2, g3f;
            un2(mul2(dd, a01), g0, g1);
            un2(mul2(dd, a23), g2, g3f);
            f2 dA01 = mk2(ex2f(g0), ex2f(g1));
            f2 dA23 = mk2(ex2f(g2), ex2f(g3f));

            float dxu = dx.x * dx.y;
            f2 du  = mk2(dxu, dxu);
            f2 b01 = mk2(bc0.x, bc0.z);
            f2 b23 = mk2(bc1.x, bc1.z);
            h01 = fma2(dA01, h01, mul2(du, b01));
            h23 = fma2(dA23, h23, mul2(du, b23));

            f2 c01 = mk2(bc0.y, bc0.w);
            f2 c23 = mk2(bc1.y, bc1.w);
            f2 ps2 = add2(mul2(h01, c01), mul2(h23, c23));
            float pa, pb; un2(ps2, pa, pb);
            float p = pa + pb;
            p += __shfl_xor_sync(0xffffffffu, p, 1);
            p += __shfl_xor_sync(0xffffffffu, p, 2);
            float ysum = fmaf(Dd, dx.y, p);

            if (jj == (tt >> 2)) {
                if      ((tt & 3) == 0) y0 = ysum;
                else if ((tt & 3) == 1) y1 = ysum;
                else if ((tt & 3) == 2) y2 = ysum;
                else                    y3 = ysum;
            }
        }
        *reinterpret_cast<float4*>(yp + tw * 16 + jj * 4) = make_float4(y0, y1, y2, y3);
        __syncthreads();
    }
    #undef ISSUE_WIN
}

// ---------------------------------------------------------------------------
extern "C" void kernel_launch(void* const* d_in, const int* in_sizes, int n_in,
                              void* d_out, int out_size)
{
    const float* xs    = (const float*)d_in[0];   // (B,K,D,L)
    const float* Alogs = (const float*)d_in[1];   // (K*D, N)
    const float* Ds    = (const float*)d_in[2];   // (K*D)
    const float* Wdt   = (const float*)d_in[3];   // (K,D,R)
    const float* bias  = (const float*)d_in[4];   // (K,D)
    const float* Wx    = (const float*)d_in[5];   // (K,C,D)
    float* out = (float*)d_out;

    k1_proj<<<BK_ * 16, 256>>>(xs, Wx, Wdt, bias);             // 256 blocks
    k2a_chunk<<<BK_ * CH * 3, 128>>>(Alogs);                   // 1536 blocks
    k2b_combine<<<(BK_ * D_ * N_) / 256, 256>>>();             // 96 blocks
    k2c_scan<<<BK_ * CH * 3, 128>>>(Alogs, Ds, out);           // 1536 blocks
}

// round 5
// speedup vs baseline: 5.8869x; 1.2568x over previous
#include <cuda_runtime.h>

// Problem constants
#define B_  4
#define K_  4
#define D_  96
#define L_  2048
#define N_  16
#define R_  6
#define C_  38          // R + 2N
#define BK_ (B_*K_)     // 16
#define CH  64          // chunks along L
#define LC  (L_/CH)     // 32 steps per chunk
#define DG_ (D_/8)      // 12 d-groups of 8

// Scratch (device globals: allocation-free, graph-safe)
// g_dx[((bk*DG + dg)*L + l)*8 + o] = {delta, x} for d = dg*8+o
// g_b[(bk*L + l)*N + n] = B_n ; g_c likewise = C_n
__device__ __align__(128) float2 g_dx[BK_ * D_ * L_];        // ~25 MB
__device__ __align__(128) float  g_b[BK_ * L_ * N_];         // 2 MB
__device__ __align__(128) float  g_c[BK_ * L_ * N_];         // 2 MB
__device__ __align__(128) float2 g_pq[BK_ * D_ * CH * N_];   // {P, q} 12.6 MB
__device__ __align__(128) float  g_h0[BK_ * D_ * CH * N_];   // chunk-entry h 6.3 MB

// ---- packed f32x2 helpers (FFMA2/FMUL2 are PTX-only) ----
typedef unsigned long long u64;
struct f2 { u64 v; };
__device__ __forceinline__ f2 mk2(float x, float y) {
    f2 r; asm("mov.b64 %0, {%1, %2};" : "=l"(r.v) : "f"(x), "f"(y)); return r;
}
__device__ __forceinline__ void un2(f2 a, float& x, float& y) {
    asm("mov.b64 {%0, %1}, %2;" : "=f"(x), "=f"(y) : "l"(a.v));
}
__device__ __forceinline__ f2 mul2(f2 a, f2 b) {
    f2 r; asm("mul.rn.f32x2 %0, %1, %2;" : "=l"(r.v) : "l"(a.v), "l"(b.v)); return r;
}
__device__ __forceinline__ f2 add2(f2 a, f2 b) {
    f2 r; asm("add.rn.f32x2 %0, %1, %2;" : "=l"(r.v) : "l"(a.v), "l"(b.v)); return r;
}
__device__ __forceinline__ f2 fma2(f2 a, f2 b, f2 c) {
    f2 r; asm("fma.rn.f32x2 %0, %1, %2, %3;" : "=l"(r.v) : "l"(a.v), "l"(b.v), "l"(c.v)); return r;
}
__device__ __forceinline__ float ex2f(float x) {
    float r; asm("ex2.approx.ftz.f32 %0, %1;" : "=f"(r) : "f"(x)); return r;
}
#define LOG2E 1.4426950408889634f

// ---- cp.async helpers ----
__device__ __forceinline__ void cpa16(unsigned saddr, const void* gptr) {
    asm volatile("cp.async.cg.shared.global [%0], [%1], 16;" :: "r"(saddr), "l"(gptr));
}
__device__ __forceinline__ void cpa_commit() { asm volatile("cp.async.commit_group;"); }
__device__ __forceinline__ void cpa_wait0()  { asm volatile("cp.async.wait_group 0;"); }

// ---------------------------------------------------------------------------
// Kernel 1: input projection + dt projection + softplus.
// 256 blocks; block = (bk, 128-l tile). Half-warps split the d-sum (48 d each),
// combine acc via one xor-16 shuffle round; half0 stores B, half1 stores C.
// ---------------------------------------------------------------------------
__global__ __launch_bounds__(256) void k1_proj(
    const float* __restrict__ xs,     // (B,K,D,L)
    const float* __restrict__ Wx,     // (K,C,D)
    const float* __restrict__ Wdt,    // (K,D,R)
    const float* __restrict__ bias)   // (K,D)
{
    __shared__ float sWp[D_][40];
    __shared__ float sWd[D_][8];
    __shared__ float sB[D_];
    __shared__ float sdts[128][8];

    const int tid  = threadIdx.x;
    const int lane = tid & 31;
    const int warp = tid >> 5;
    const int bk   = blockIdx.x >> 4;
    const int k    = bk & (K_ - 1);
    const int lblk = (blockIdx.x & 15) << 7;      // 128 l per block
    const int half = lane >> 4;
    const int li   = (warp << 4) | (lane & 15);   // [0,128)
    const int l    = lblk + li;

    for (int i = tid; i < C_ * D_; i += 256) {
        int c = i / D_, d = i - c * D_;
        sWp[d][c] = Wx[k * C_ * D_ + i];
    }
    for (int i = tid; i < D_ * R_; i += 256) {
        int d = i / R_, r = i - d * R_;
        sWd[d][r] = Wdt[k * D_ * R_ + i];
    }
    if (tid < D_) {
        sWp[tid][38] = 0.f; sWp[tid][39] = 0.f;
        sWd[tid][6]  = 0.f; sWd[tid][7]  = 0.f;
        sB[tid] = bias[k * D_ + tid];
    }
    __syncthreads();

    float acc[40];
    #pragma unroll
    for (int c = 0; c < 40; c++) acc[c] = 0.f;

    // Each half-warp sums 48 d's
    const float* __restrict__ xp = xs + ((size_t)bk * D_ + half * 48) * L_ + l;
    #pragma unroll 8
    for (int dd = 0; dd < 48; dd++) {
        float x = xp[(size_t)dd * L_];
        const float4* wr = reinterpret_cast<const float4*>(&sWp[half * 48 + dd][0]);
        #pragma unroll
        for (int j = 0; j < 10; j++) {
            float4 w = wr[j];
            acc[4*j+0] = fmaf(w.x, x, acc[4*j+0]);
            acc[4*j+1] = fmaf(w.y, x, acc[4*j+1]);
            acc[4*j+2] = fmaf(w.z, x, acc[4*j+2]);
            acc[4*j+3] = fmaf(w.w, x, acc[4*j+3]);
        }
    }
    // combine the two halves
    #pragma unroll
    for (int c = 0; c < C_; c++)
        acc[c] += __shfl_xor_sync(0xffffffffu, acc[c], 16);

    // half 0 stores B (acc[6..22)); half 1 stores C (acc[22..38))
    if (half == 0) {
        float4* dst = reinterpret_cast<float4*>(g_b) + ((size_t)bk * L_ + l) * 4;
        #pragma unroll
        for (int j = 0; j < 4; j++)
            dst[j] = make_float4(acc[R_+4*j], acc[R_+4*j+1], acc[R_+4*j+2], acc[R_+4*j+3]);
        #pragma unroll
        for (int r = 0; r < R_; r++) sdts[li][r] = acc[r];
    } else {
        float4* dst = reinterpret_cast<float4*>(g_c) + ((size_t)bk * L_ + l) * 4;
        #pragma unroll
        for (int j = 0; j < 4; j++)
            dst[j] = make_float4(acc[R_+N_+4*j], acc[R_+N_+4*j+1],
                                 acc[R_+N_+4*j+2], acc[R_+N_+4*j+3]);
    }
    __syncthreads();

    // Phase 2: thread = (lq = tid>>3 in [0,32), o = tid&7); 4 l's each
    const int lq = tid >> 3;
    const int o  = tid & 7;
    #pragma unroll
    for (int i = 0; i < 4; i++) {
        const int lt = lq + 32 * i;
        const int l2 = lblk + lt;
        #pragma unroll 2
        for (int dg = 0; dg < DG_; dg++) {
            const int d = dg * 8 + o;
            float t = sB[d];
            #pragma unroll
            for (int r = 0; r < R_; r++) t = fmaf(sWd[d][r], sdts[lt][r], t);
            float sp = (t > 15.f) ? t : __logf(1.f + __expf(t));
            float x  = xs[((size_t)bk * D_ + d) * L_ + l2];
            g_dx[(((size_t)bk * DG_ + dg) * L_ + l2) * 8 + o] = make_float2(sp, x);
        }
    }
}

// ---------------------------------------------------------------------------
// Pass A: per-chunk local scan q (h0=0) and decay P = exp2(A2 * sum(delta)).
// Single-shot cp.async of the whole chunk (dx 8KB + B 2KB), one barrier,
// then 32 straight steps. Warp = 8 d (octant o) x 16 n (quad jj).
// ---------------------------------------------------------------------------
__global__ __launch_bounds__(128) void k2a_chunk(
    const float* __restrict__ Alogs)  // (K*D, N)
{
    __shared__ __align__(16) float4 s_dx4[512];
    __shared__ __align__(16) float  s_b[LC * N_];

    const int tid  = threadIdx.x;
    const int lane = tid & 31;
    const int warp = tid >> 5;
    const int o    = lane >> 2;
    const int jj   = lane & 3;
    const int g3   = blockIdx.x % 3;
    const int c    = (blockIdx.x / 3) & (CH - 1);
    const int bk   = blockIdx.x / (3 * CH);
    const int dg   = g3 * 4 + warp;
    const int d    = dg * 8 + o;
    const int k    = bk & (K_ - 1);
    const int kd   = k * D_ + d;
    const int n0   = jj * 4;
    const int l0   = c * LC;

    const unsigned sdb = (unsigned)__cvta_generic_to_shared(s_dx4);
    const unsigned sbb = (unsigned)__cvta_generic_to_shared(s_b);
    const float4* dxsrc = reinterpret_cast<const float4*>(g_dx);

    #pragma unroll
    for (int j = 0; j < 4; j++) {
        int i = tid + j * 128, w = i >> 7, r = i & 127;
        cpa16(sdb + (unsigned)(i * 16),
              dxsrc + (((size_t)bk * DG_ + g3 * 4 + w) * L_ + l0) * 4 + r);
    }
    cpa16(sbb + (unsigned)(tid * 16),
          reinterpret_cast<const float4*>(g_b + ((size_t)bk * L_ + l0) * 16) + tid);
    cpa_commit();

    float4 al = *reinterpret_cast<const float4*>(&Alogs[kd * N_ + n0]);
    const f2 a01 = mk2(-__expf(al.x) * LOG2E, -__expf(al.y) * LOG2E);
    const f2 a23 = mk2(-__expf(al.z) * LOG2E, -__expf(al.w) * LOG2E);

    cpa_wait0();
    __syncthreads();

    const float2* __restrict__ sdx = reinterpret_cast<const float2*>(s_dx4);
    f2 h01 = mk2(0.f, 0.f), h23 = mk2(0.f, 0.f);
    float dsum = 0.f;

    #pragma unroll 8
    for (int tt = 0; tt < LC; tt++) {
        float4 b4 = *reinterpret_cast<const float4*>(&s_b[tt * N_ + n0]);
        float2 dx = sdx[(warp * LC + tt) * 8 + o];

        f2 dd = mk2(dx.x, dx.x);
        float e0, e1, e2, e3;
        un2(mul2(dd, a01), e0, e1);
        un2(mul2(dd, a23), e2, e3);
        f2 dA01 = mk2(ex2f(e0), ex2f(e1));
        f2 dA23 = mk2(ex2f(e2), ex2f(e3));

        float dxu = dx.x * dx.y;
        f2 du = mk2(dxu, dxu);
        h01 = fma2(dA01, h01, mul2(du, mk2(b4.x, b4.y)));
        h23 = fma2(dA23, h23, mul2(du, mk2(b4.z, b4.w)));
        dsum += dx.x;
    }

    float a0, a1, a2, a3, q0, q1, q2, q3;
    un2(a01, a0, a1); un2(a23, a2, a3);
    un2(h01, q0, q1); un2(h23, q2, q3);
    float4* dst = reinterpret_cast<float4*>(g_pq)
                  + ((((size_t)bk * D_ + d) * CH + c) * N_ + n0) / 2;
    dst[0] = make_float4(ex2f(a0 * dsum), q0, ex2f(a1 * dsum), q1);
    dst[1] = make_float4(ex2f(a2 * dsum), q2, ex2f(a3 * dsum), q3);
}

// ---------------------------------------------------------------------------
// Pass B: block per (bkd). Coalesced 8KB load to smem, 16-lane serial scan,
// coalesced h0 store. Grid 1536 x 128.
// ---------------------------------------------------------------------------
__global__ __launch_bounds__(128) void k2b_combine()
{
    __shared__ float2 s_pq[CH * N_];
    __shared__ float  s_h0[CH * N_];

    const int tid = threadIdx.x;
    const size_t base = (size_t)blockIdx.x * CH * N_;

    #pragma unroll
    for (int i = tid; i < CH * N_; i += 128) s_pq[i] = g_pq[base + i];
    __syncthreads();

    if (tid < N_) {
        float h = 0.f;
        #pragma unroll 8
        for (int c2 = 0; c2 < CH; c2++) {
            s_h0[c2 * N_ + tid] = h;
            float2 pq = s_pq[c2 * N_ + tid];
            h = fmaf(pq.x, h, pq.y);
        }
    }
    __syncthreads();

    #pragma unroll
    for (int i = tid; i < CH * N_; i += 128) g_h0[base + i] = s_h0[i];
}

// ---------------------------------------------------------------------------
// Pass C: re-scan from known entry state. Single-shot cp.async (dx+B+C),
// one barrier, 32 straight steps; quad-reduce; STG.128 per 16-step window.
// ---------------------------------------------------------------------------
__global__ __launch_bounds__(128) void k2c_scan(
    const float* __restrict__ Alogs,  // (K*D, N)
    const float* __restrict__ Ds,     // (K*D)
    float* __restrict__ out)          // (B,K,D,L)
{
    __shared__ __align__(16) float4 s_dx4[512];
    __shared__ __align__(16) float  s_b[LC * N_];
    __shared__ __align__(16) float  s_c[LC * N_];

    const int tid  = threadIdx.x;
    const int lane = tid & 31;
    const int warp = tid >> 5;
    const int o    = lane >> 2;
    const int jj   = lane & 3;
    const int g3   = blockIdx.x % 3;
    const int c    = (blockIdx.x / 3) & (CH - 1);
    const int bk   = blockIdx.x / (3 * CH);
    const int dg   = g3 * 4 + warp;
    const int d    = dg * 8 + o;
    const int k    = bk & (K_ - 1);
    const int kd   = k * D_ + d;
    const int n0   = jj * 4;
    const int l0   = c * LC;

    const unsigned sdb = (unsigned)__cvta_generic_to_shared(s_dx4);
    const unsigned sbb = (unsigned)__cvta_generic_to_shared(s_b);
    const unsigned scb = (unsigned)__cvta_generic_to_shared(s_c);
    const float4* dxsrc = reinterpret_cast<const float4*>(g_dx);

    #pragma unroll
    for (int j = 0; j < 4; j++) {
        int i = tid + j * 128, w = i >> 7, r = i & 127;
        cpa16(sdb + (unsigned)(i * 16),
              dxsrc + (((size_t)bk * DG_ + g3 * 4 + w) * L_ + l0) * 4 + r);
    }
    cpa16(sbb + (unsigned)(tid * 16),
          reinterpret_cast<const float4*>(g_b + ((size_t)bk * L_ + l0) * 16) + tid);
    cpa16(scb + (unsigned)(tid * 16),
          reinterpret_cast<const float4*>(g_c + ((size_t)bk * L_ + l0) * 16) + tid);
    cpa_commit();

    float4 al = *reinterpret_cast<const float4*>(&Alogs[kd * N_ + n0]);
    const f2 a01 = mk2(-__expf(al.x) * LOG2E, -__expf(al.y) * LOG2E);
    const f2 a23 = mk2(-__expf(al.z) * LOG2E, -__expf(al.w) * LOG2E);
    const float Dd = Ds[kd];
    float4 h0v = *reinterpret_cast<const float4*>(
        &g_h0[(((size_t)bk * D_ + d) * CH + c) * N_ + n0]);

    cpa_wait0();
    __syncthreads();

    const float2* __restrict__ sdx = reinterpret_cast<const float2*>(s_dx4);
    f2 h01 = mk2(h0v.x, h0v.y), h23 = mk2(h0v.z, h0v.w);
    float* __restrict__ yp = out + ((size_t)bk * D_ + d) * L_ + l0;

    #pragma unroll
    for (int tw = 0; tw < 2; tw++) {
        float y0 = 0.f, y1 = 0.f, y2 = 0.f, y3 = 0.f;
        #pragma unroll
        for (int t2 = 0; t2 < 16; t2++) {
            const int tt = tw * 16 + t2;
            float4 b4 = *reinterpret_cast<const float4*>(&s_b[tt * N_ + n0]);
            float4 c4 = *reinterpret_cast<const float4*>(&s_c[tt * N_ + n0]);
            float2 dx = sdx[(warp * LC + tt) * 8 + o];

            f2 dd = mk2(dx.x, dx.x);
            float e0, e1, e2, e3;
            un2(mul2(dd, a01), e0, e1);
            un2(mul2(dd, a23), e2, e3);
            f2 dA01 = mk2(ex2f(e0), ex2f(e1));
            f2 dA23 = mk2(ex2f(e2), ex2f(e3));

            float dxu = dx.x * dx.y;
            f2 du = mk2(dxu, dxu);
            h01 = fma2(dA01, h01, mul2(du, mk2(b4.x, b4.y)));
            h23 = fma2(dA23, h23, mul2(du, mk2(b4.z, b4.w)));

            f2 ps2 = add2(mul2(h01, mk2(c4.x, c4.y)), mul2(h23, mk2(c4.z, c4.w)));
            float pa, pb; un2(ps2, pa, pb);
            float p = pa + pb;
            p += __shfl_xor_sync(0xffffffffu, p, 1);
            p += __shfl_xor_sync(0xffffffffu, p, 2);
            float ysum = fmaf(Dd, dx.y, p);

            if (jj == (t2 >> 2)) {
                if      ((t2 & 3) == 0) y0 = ysum;
                else if ((t2 & 3) == 1) y1 = ysum;
                else if ((t2 & 3) == 2) y2 = ysum;
                else                    y3 = ysum;
            }
        }
        *reinterpret_cast<float4*>(yp + tw * 16 + jj * 4) = make_float4(y0, y1, y2, y3);
    }
}

// ---------------------------------------------------------------------------
extern "C" void kernel_launch(void* const* d_in, const int* in_sizes, int n_in,
                              void* d_out, int out_size)
{
    const float* xs    = (const float*)d_in[0];   // (B,K,D,L)
    const float* Alogs = (const float*)d_in[1];   // (K*D, N)
    const float* Ds    = (const float*)d_in[2];   // (K*D)
    const float* Wdt   = (const float*)d_in[3];   // (K,D,R)
    const float* bias  = (const float*)d_in[4];   // (K,D)
    const float* Wx    = (const float*)d_in[5];   // (K,C,D)
    float* out = (float*)d_out;

    k1_proj<<<BK_ * 16, 256>>>(xs, Wx, Wdt, bias);             // 256 blocks
    k2a_chunk<<<BK_ * CH * 3, 128>>>(Alogs);                   // 3072 blocks
    k2b_combine<<<BK_ * D_, 128>>>();                          // 1536 blocks
    k2c_scan<<<BK_ * CH * 3, 128>>>(Alogs, Ds, out);           // 3072 blocks
}